// round 6
// baseline (speedup 1.0000x reference)
#include <cuda_runtime.h>
#include <cuda_bf16.h>
#include <cstdint>

// ---------------- problem constants ----------------
#define NB      8
#define LQ      2500
#define DM      256
#define NH      8
#define NL      4
#define NP      8
#define NZ      4
#define DH      32
#define LEN_IN  14960
#define KDIM    256

__device__ __constant__ int c_H[NL]  = {64, 32, 16, 8};
__device__ __constant__ int c_W[NL]  = {176, 88, 44, 22};
__device__ __constant__ int c_ST[NL] = {0, 11264, 14080, 14784};

// ---------------- scratch ----------
__device__ float g_value [(size_t)NB * LEN_IN * DM];
__device__ float g_offawl[(size_t)NB * LQ * 768];   // cols 0..511 = off, 512..767 = awl
__device__ float g_b768  [768];

__device__ __nv_bfloat16 g_vhi[(size_t)NB * LEN_IN * KDIM];
__device__ __nv_bfloat16 g_vlo[(size_t)NB * LEN_IN * KDIM];
__device__ __nv_bfloat16 g_qhi[(size_t)NB * LQ * KDIM];
__device__ __nv_bfloat16 g_qlo[(size_t)NB * LQ * KDIM];
__device__ __nv_bfloat16 g_wvhi[KDIM * 256], g_wvlo[KDIM * 256];   // Wv [K][256]
__device__ __nv_bfloat16 g_wqhi[KDIM * 768], g_wqlo[KDIM * 768];   // [Wo|Wa] [K][768]

// =====================================================================
// Split pass: fp32 -> bf16 hi + bf16 lo (residual), layout preserved
// =====================================================================
__global__ void split_kernel(const float* __restrict__ src,
                             __nv_bfloat16* __restrict__ hi,
                             __nv_bfloat16* __restrict__ lo, int n4) {
    int i = blockIdx.x * blockDim.x + threadIdx.x;
    if (i >= n4) return;
    float4 v = reinterpret_cast<const float4*>(src)[i];
    __nv_bfloat16 h0 = __float2bfloat16(v.x);
    __nv_bfloat16 h1 = __float2bfloat16(v.y);
    __nv_bfloat16 h2 = __float2bfloat16(v.z);
    __nv_bfloat16 h3 = __float2bfloat16(v.w);
    __nv_bfloat16 l0 = __float2bfloat16(v.x - __bfloat162float(h0));
    __nv_bfloat16 l1 = __float2bfloat16(v.y - __bfloat162float(h1));
    __nv_bfloat16 l2 = __float2bfloat16(v.z - __bfloat162float(h2));
    __nv_bfloat16 l3 = __float2bfloat16(v.w - __bfloat162float(h3));
    ushort4 hu = make_ushort4(*(unsigned short*)&h0, *(unsigned short*)&h1,
                              *(unsigned short*)&h2, *(unsigned short*)&h3);
    ushort4 lu = make_ushort4(*(unsigned short*)&l0, *(unsigned short*)&l1,
                              *(unsigned short*)&l2, *(unsigned short*)&l3);
    reinterpret_cast<ushort4*>(hi)[i] = hu;
    reinterpret_cast<ushort4*>(lo)[i] = lu;
}

// Column-placing split: W[K][Ncols] fp32 -> dst[k][colOff + n] bf16 hi/lo, pitch Ntot
__global__ void csplit_kernel(const float* __restrict__ W,
                              __nv_bfloat16* __restrict__ hi,
                              __nv_bfloat16* __restrict__ lo,
                              int Ncols, int colOff, int Ntot) {
    int i = blockIdx.x * blockDim.x + threadIdx.x;
    if (i >= KDIM * Ncols) return;
    int k = i / Ncols, n = i % Ncols;
    float v = W[i];
    __nv_bfloat16 h = __float2bfloat16(v);
    __nv_bfloat16 l = __float2bfloat16(v - __bfloat162float(h));
    size_t d = (size_t)k * Ntot + colOff + n;
    hi[d] = h; lo[d] = l;
}

// bias concat: [bo(512) | ba(256)] -> g_b768
__global__ void biascat_kernel(const float* __restrict__ bo,
                               const float* __restrict__ ba,
                               float* __restrict__ dst) {
    int i = threadIdx.x + blockIdx.x * blockDim.x;
    if (i < 512) dst[i] = bo[i];
    else if (i < 768) dst[i] = ba[i - 512];
}

// =====================================================================
// bf16x3 GEMM (mma.sync path — tcgen05 unavailable under compute_103 PTX)
// C(MxN) = Ahi@Bhi + Ahi@Blo + Alo@Bhi + bias ;  K = 256
// BM=128 BN=64 BK=64, 256 threads = 8 warps (4M x 2N), warp tile 32x32
// cp.async 2-stage double buffering, ldmatrix fragment loads.
// =====================================================================
#define BM 128
#define BN 64
#define BK 64
#define AP 72          // A smem pitch elems (144 B = 9 x 16B, ldsm conflict-free)
#define BP 72          // B smem pitch elems (B stored [k][n], 64 n-cols used)
#define OFF_AH 0
#define OFF_AL 9216    // 128*72
#define OFF_BH 18432
#define OFF_BL 23040   // + 64*72
#define STAGE_ELEMS 27648
#define SMEM_BYTES (STAGE_ELEMS * 2 * 2)   // 110592

__device__ __forceinline__ void cp16(uint32_t dst, const void* src, bool v) {
    asm volatile("cp.async.ca.shared.global [%0], [%1], 16, %2;\n"
                 :: "r"(dst), "l"(src), "r"(v ? 16 : 0));
}
__device__ __forceinline__ void ldsm4(uint32_t r[4], uint32_t a) {
    asm volatile("ldmatrix.sync.aligned.m8n8.x4.shared.b16 {%0,%1,%2,%3}, [%4];"
                 : "=r"(r[0]), "=r"(r[1]), "=r"(r[2]), "=r"(r[3]) : "r"(a));
}
__device__ __forceinline__ void ldsm4t(uint32_t r[4], uint32_t a) {
    asm volatile("ldmatrix.sync.aligned.m8n8.x4.trans.shared.b16 {%0,%1,%2,%3}, [%4];"
                 : "=r"(r[0]), "=r"(r[1]), "=r"(r[2]), "=r"(r[3]) : "r"(a));
}
__device__ __forceinline__ void mma16816(float c[4], const uint32_t a[4],
                                         uint32_t b0, uint32_t b1) {
    asm volatile(
        "mma.sync.aligned.m16n8k16.row.col.f32.bf16.bf16.f32 "
        "{%0,%1,%2,%3}, {%4,%5,%6,%7}, {%8,%9}, {%0,%1,%2,%3};"
        : "+f"(c[0]), "+f"(c[1]), "+f"(c[2]), "+f"(c[3])
        : "r"(a[0]), "r"(a[1]), "r"(a[2]), "r"(a[3]), "r"(b0), "r"(b1));
}

__global__ __launch_bounds__(256, 2)
void gemm_split3_kernel(const __nv_bfloat16* __restrict__ Ahi,
                        const __nv_bfloat16* __restrict__ Alo,
                        const __nv_bfloat16* __restrict__ Bhi,   // [K][N]
                        const __nv_bfloat16* __restrict__ Blo,
                        const float* __restrict__ bias,
                        float* __restrict__ C, int M, int N) {
    extern __shared__ __nv_bfloat16 sm[];
    const uint32_t smb = (uint32_t)__cvta_generic_to_shared(sm);

    const int bn = blockIdx.x * BN;      // bn fastest -> A slab shared in L2
    const int bm = blockIdx.y * BM;
    const int t = threadIdx.x, lane = t & 31, wid = t >> 5;
    const int wM = (wid & 3) * 32, wN = (wid >> 2) * 32;

    // loaders
    const int a_row = t >> 1;            // 0..127
    const int a_seg = (t & 1) * 4;       // 16B chunks {0..3} or {4..7}
    const bool a_v  = (bm + a_row) < M;
    const size_t a_rowoff = (size_t)(a_v ? bm + a_row : 0) * KDIM;
    const int b_r  = t >> 3;             // 0..31 (k), rows b_r and b_r+32
    const int b_cs = t & 7;              // n chunk 0..7

    float acc[2][4][4];
#pragma unroll
    for (int i = 0; i < 2; i++)
#pragma unroll
        for (int j = 0; j < 4; j++)
#pragma unroll
            for (int k = 0; k < 4; k++) acc[i][j][k] = 0.f;

    auto load_stage = [&](int s, int k0) {
        const uint32_t base = smb + (uint32_t)(s * STAGE_ELEMS) * 2;
        const uint32_t ah = base + (uint32_t)(OFF_AH + a_row * AP) * 2;
        const uint32_t al = base + (uint32_t)(OFF_AL + a_row * AP) * 2;
#pragma unroll
        for (int i = 0; i < 4; i++) {
            cp16(ah + (a_seg + i) * 16, Ahi + a_rowoff + k0 + (a_seg + i) * 8, a_v);
            cp16(al + (a_seg + i) * 16, Alo + a_rowoff + k0 + (a_seg + i) * 8, a_v);
        }
#pragma unroll
        for (int g = 0; g < 2; g++) {
            const int kr = b_r + g * 32;
            const size_t bs = (size_t)(k0 + kr) * N + bn + b_cs * 8;
            cp16(base + (uint32_t)(OFF_BH + kr * BP + b_cs * 8) * 2, Bhi + bs, true);
            cp16(base + (uint32_t)(OFF_BL + kr * BP + b_cs * 8) * 2, Blo + bs, true);
        }
    };

    load_stage(0, 0);
    asm volatile("cp.async.commit_group;\n");
    load_stage(1, BK);
    asm volatile("cp.async.commit_group;\n");

    const int NIT = KDIM / BK;   // 4
#pragma unroll
    for (int it = 0; it < NIT; it++) {
        if (it < NIT - 1) asm volatile("cp.async.wait_group 1;\n");
        else              asm volatile("cp.async.wait_group 0;\n");
        __syncthreads();

        const int s = it & 1;
        const uint32_t base = smb + (uint32_t)(s * STAGE_ELEMS) * 2;
        const uint32_t abaseH = base + (uint32_t)OFF_AH * 2;
        const uint32_t abaseL = base + (uint32_t)OFF_AL * 2;
        const uint32_t bbaseH = base + (uint32_t)OFF_BH * 2;
        const uint32_t bbaseL = base + (uint32_t)OFF_BL * 2;

#pragma unroll
        for (int ks = 0; ks < BK; ks += 16) {
            uint32_t ah[2][4], al[2][4], bh[4][2], bl[4][2];
#pragma unroll
            for (int mt = 0; mt < 2; mt++) {
                const int r = wM + mt * 16 + (lane & 15);
                const int c = ks + (lane >> 4) * 8;
                ldsm4(ah[mt], abaseH + (uint32_t)(r * AP + c) * 2);
                ldsm4(al[mt], abaseL + (uint32_t)(r * AP + c) * 2);
            }
#pragma unroll
            for (int g = 0; g < 2; g++) {
                const int r = ks + (lane & 15);
                const int c = wN + g * 16 + (lane >> 4) * 8;
                uint32_t rb[4];
                ldsm4t(rb, bbaseH + (uint32_t)(r * BP + c) * 2);
                bh[g*2+0][0] = rb[0]; bh[g*2+0][1] = rb[1];
                bh[g*2+1][0] = rb[2]; bh[g*2+1][1] = rb[3];
                ldsm4t(rb, bbaseL + (uint32_t)(r * BP + c) * 2);
                bl[g*2+0][0] = rb[0]; bl[g*2+0][1] = rb[1];
                bl[g*2+1][0] = rb[2]; bl[g*2+1][1] = rb[3];
            }
#pragma unroll
            for (int mt = 0; mt < 2; mt++)
#pragma unroll
                for (int nt = 0; nt < 4; nt++) {
                    mma16816(acc[mt][nt], ah[mt], bh[nt][0], bh[nt][1]);
                    mma16816(acc[mt][nt], ah[mt], bl[nt][0], bl[nt][1]);
                    mma16816(acc[mt][nt], al[mt], bh[nt][0], bh[nt][1]);
                }
        }
        __syncthreads();
        if (it + 2 < NIT) {
            load_stage(s, (it + 2) * BK);
            asm volatile("cp.async.commit_group;\n");
        }
    }

    // epilogue
    const int gr = lane >> 2;
    const int kq = (lane & 3) * 2;
#pragma unroll
    for (int mt = 0; mt < 2; mt++) {
#pragma unroll
        for (int nt = 0; nt < 4; nt++) {
            const int col = bn + wN + nt * 8 + kq;
            const float2 bb = *reinterpret_cast<const float2*>(&bias[col]);
            const int r0 = bm + wM + mt * 16 + gr;
            if (r0 < M) {
                float2 o; o.x = acc[mt][nt][0] + bb.x; o.y = acc[mt][nt][1] + bb.y;
                *reinterpret_cast<float2*>(&C[(size_t)r0 * N + col]) = o;
            }
            if (r0 + 8 < M) {
                float2 o; o.x = acc[mt][nt][2] + bb.x; o.y = acc[mt][nt][3] + bb.y;
                *reinterpret_cast<float2*>(&C[(size_t)(r0 + 8) * N + col]) = o;
            }
        }
    }
}

// =====================================================================
// Sampling kernel (reads combined off/awl buffer)
// =====================================================================
__global__ __launch_bounds__(256)
void msda_sample_kernel(const float* __restrict__ ref,
                        const float* __restrict__ offawl,  // (N*LQ, 768)
                        const float* __restrict__ value,
                        float* __restrict__ out)
{
    __shared__ int4   s_addr[NH * 32];
    __shared__ float4 s_w[NH * 32];

    const int nq = blockIdx.x;
    const int n  = nq / LQ;
    const int t  = threadIdx.x;
    const int h  = t >> 5;
    const int j  = t & 31;

    {
        const float* rowp = offawl + (size_t)nq * 768;
        const float logit = rowp[512 + h * 32 + j];
        float m = logit;
#pragma unroll
        for (int s = 16; s > 0; s >>= 1) m = fmaxf(m, __shfl_xor_sync(0xffffffffu, m, s));
        const float e = __expf(logit - m);
        float ssum = e;
#pragma unroll
        for (int s = 16; s > 0; s >>= 1) ssum += __shfl_xor_sync(0xffffffffu, ssum, s);
        const float wgt = e / ssum;

        const float ox = rowp[h * 64 + j * 2 + 0];
        const float oy = rowp[h * 64 + j * 2 + 1];

        const int l = j >> 3;
        const int z = j & 3;
        const float rx = ref[((size_t)nq * NZ + z) * 2 + 0];
        const float ry = ref[((size_t)nq * NZ + z) * 2 + 1];

        const int   hl = c_H[l];
        const int   wl = c_W[l];
        const int   st = c_ST[l];
        const float fhl = (float)hl;
        const float fwl = (float)wl;

        const float x = (rx + __fdividef(ox, fwl)) * fwl - 0.5f;
        const float y = (ry + __fdividef(oy, fhl)) * fhl - 0.5f;

        const float x0f = floorf(x);
        const float y0f = floorf(y);
        const float wx = x - x0f;
        const float wy = y - y0f;
        const int x0 = (int)x0f, y0 = (int)y0f;
        const int x1 = x0 + 1,   y1 = y0 + 1;

        const bool vx0 = (x0 >= 0) & (x0 < wl);
        const bool vx1 = (x1 >= 0) & (x1 < wl);
        const bool vy0 = (y0 >= 0) & (y0 < hl);
        const bool vy1 = (y1 >= 0) & (y1 < hl);

        const bool v00 = vx0 & vy0, v10 = vx1 & vy0;
        const bool v01 = vx0 & vy1, v11 = vx1 & vy1;

        int4 a;
        a.x = v00 ? (st + y0 * wl + x0) * DM : 0;
        a.y = v10 ? (st + y0 * wl + x1) * DM : 0;
        a.z = v01 ? (st + y1 * wl + x0) * DM : 0;
        a.w = v11 ? (st + y1 * wl + x1) * DM : 0;

        float4 w4;
        w4.x = v00 ? wgt * (1.f - wx) * (1.f - wy) : 0.f;
        w4.y = v10 ? wgt * wx * (1.f - wy)         : 0.f;
        w4.z = v01 ? wgt * (1.f - wx) * wy         : 0.f;
        w4.w = v11 ? wgt * wx * wy                 : 0.f;

        s_addr[t] = a;
        s_w[t]    = w4;
    }
    __syncthreads();

    const float* __restrict__ vb = value + (size_t)n * LEN_IN * DM + h * DH + j;

    float acc = 0.f;
#pragma unroll 8
    for (int s = 0; s < 32; s++) {
        const int4   a  = s_addr[h * 32 + s];
        const float4 w4 = s_w[h * 32 + s];
        acc += w4.x * __ldg(vb + a.x);
        acc += w4.y * __ldg(vb + a.y);
        acc += w4.z * __ldg(vb + a.z);
        acc += w4.w * __ldg(vb + a.w);
    }

    out[(size_t)nq * DM + h * DH + j] = acc;
}

// ---------------- launch ----------------------------------------------------
extern "C" void kernel_launch(void* const* d_in, const int* in_sizes, int n_in,
                              void* d_out, int out_size) {
    const float* query  = (const float*)d_in[0];
    const float* refpts = (const float*)d_in[2];
    const float* inflat = (const float*)d_in[3];
    const float* Wv = (const float*)d_in[6];
    const float* bv = (const float*)d_in[7];
    const float* Wo = (const float*)d_in[8];
    const float* bo = (const float*)d_in[9];
    const float* Wa = (const float*)d_in[10];
    const float* ba = (const float*)d_in[11];
    float* out = (float*)d_out;

    float *valuep, *offawlp, *b768p;
    cudaGetSymbolAddress((void**)&valuep,  g_value);
    cudaGetSymbolAddress((void**)&offawlp, g_offawl);
    cudaGetSymbolAddress((void**)&b768p,   g_b768);

    __nv_bfloat16 *vhi, *vlo, *qhi, *qlo, *wvhi, *wvlo, *wqhi, *wqlo;
    cudaGetSymbolAddress((void**)&vhi,  g_vhi);
    cudaGetSymbolAddress((void**)&vlo,  g_vlo);
    cudaGetSymbolAddress((void**)&qhi,  g_qhi);
    cudaGetSymbolAddress((void**)&qlo,  g_qlo);
    cudaGetSymbolAddress((void**)&wvhi, g_wvhi);
    cudaGetSymbolAddress((void**)&wvlo, g_wvlo);
    cudaGetSymbolAddress((void**)&wqhi, g_wqhi);
    cudaGetSymbolAddress((void**)&wqlo, g_wqlo);

    cudaFuncSetAttribute(gemm_split3_kernel,
                         cudaFuncAttributeMaxDynamicSharedMemorySize, SMEM_BYTES);

    const int Mv = NB * LEN_IN;   // 119680
    const int Mq = NB * LQ;       // 20000

    // splits
    {
        int n4 = Mv * KDIM / 4;
        split_kernel<<<(n4 + 255) / 256, 256>>>(inflat, vhi, vlo, n4);
    }
    {
        int n4 = Mq * KDIM / 4;
        split_kernel<<<(n4 + 255) / 256, 256>>>(query, qhi, qlo, n4);
    }
    {
        int n4 = KDIM * 256 / 4;
        split_kernel<<<(n4 + 255) / 256, 256>>>(Wv, wvhi, wvlo, n4);
    }
    csplit_kernel<<<(KDIM * 512 + 255) / 256, 256>>>(Wo, wqhi, wqlo, 512, 0, 768);
    csplit_kernel<<<(KDIM * 256 + 255) / 256, 256>>>(Wa, wqhi, wqlo, 256, 512, 768);
    biascat_kernel<<<3, 256>>>(bo, ba, b768p);

    // GEMMs
    {
        dim3 grid(256 / BN, Mv / BM);             // 4 x 935
        gemm_split3_kernel<<<grid, 256, SMEM_BYTES>>>(vhi, vlo, wvhi, wvlo, bv,
                                                      valuep, Mv, 256);
    }
    {
        dim3 grid(768 / BN, (Mq + BM - 1) / BM);  // 12 x 157
        gemm_split3_kernel<<<grid, 256, SMEM_BYTES>>>(qhi, qlo, wqhi, wqlo, b768p,
                                                      offawlp, Mq, 768);
    }

    msda_sample_kernel<<<Mq, 256>>>(refpts, offawlp, valuep, out);
}